// round 14
// baseline (speedup 1.0000x reference)
#include <cuda_runtime.h>
#include <cuda_bf16.h>
#include <cstdint>

#define B_  4
#define S_  2048
#define H_  1024
#define NH_ 16
#define HD_ 64

#define LOG2E 1.4426950408889634f
#define PADW 24   // proj: bf16 elems per SMEM row (48B), Kc=16

// ---------------------------------------------------------------------------
__device__ __nv_bfloat16 g_Xh[B_ * S_ * H_];
__device__ __nv_bfloat16 g_Xl[B_ * S_ * H_];
__device__ __nv_bfloat16 g_Wh[3][H_ * H_];   // W^T: [N][K]
__device__ __nv_bfloat16 g_Wl[3][H_ * H_];
__device__ __nv_bfloat16 g_Ph[3][B_ * NH_ * S_ * HD_];  // Q/K/V hi, [bh][s][d]
__device__ __nv_bfloat16 g_Pl[3][B_ * NH_ * S_ * HD_];  // Q/K/V lo

// ---------------------------------------------------------------------------
__device__ __forceinline__ uint32_t smem_to_u32(const void* p) {
    uint32_t a;
    asm("{ .reg .u64 t; cvta.to.shared.u64 t, %1; cvt.u32.u64 %0, t; }"
        : "=r"(a) : "l"(p));
    return a;
}

__device__ __forceinline__ void mma_bf16(float* c, const uint32_t* a, const uint32_t* b) {
    asm volatile(
        "mma.sync.aligned.m16n8k16.row.col.f32.bf16.bf16.f32 "
        "{%0,%1,%2,%3}, {%4,%5,%6,%7}, {%8,%9}, {%0,%1,%2,%3};"
        : "+f"(c[0]), "+f"(c[1]), "+f"(c[2]), "+f"(c[3])
        : "r"(a[0]), "r"(a[1]), "r"(a[2]), "r"(a[3]), "r"(b[0]), "r"(b[1]));
}

__device__ __forceinline__ void ldm_x4(uint32_t* r, uint32_t addr) {
    asm volatile("ldmatrix.sync.aligned.m8n8.x4.shared.b16 {%0,%1,%2,%3}, [%4];"
        : "=r"(r[0]), "=r"(r[1]), "=r"(r[2]), "=r"(r[3]) : "r"(addr));
}
__device__ __forceinline__ void ldm_x4t(uint32_t* r, uint32_t addr) {
    asm volatile("ldmatrix.sync.aligned.m8n8.x4.trans.shared.b16 {%0,%1,%2,%3}, [%4];"
        : "=r"(r[0]), "=r"(r[1]), "=r"(r[2]), "=r"(r[3]) : "r"(addr));
}

#define CP_ASYNC16(dst, src) \
    asm volatile("cp.async.cg.shared.global [%0], [%1], 16;" :: "r"(dst), "l"(src))
#define CP_COMMIT() asm volatile("cp.async.commit_group;")
#define CP_WAIT2()  asm volatile("cp.async.wait_group 2;" ::: "memory")
#define CP_WAIT1()  asm volatile("cp.async.wait_group 1;" ::: "memory")
#define CP_WAIT0()  asm volatile("cp.async.wait_group 0;" ::: "memory")

__device__ __forceinline__ float ex2(float x) {
    float y;
    asm("ex2.approx.ftz.f32 %0, %1;" : "=f"(y) : "f"(x));
    return y;
}

__device__ __forceinline__ void split2(float x, __nv_bfloat16& h, __nv_bfloat16& l) {
    h = __float2bfloat16(x);
    l = __float2bfloat16(x - __bfloat162float(h));
}
__device__ __forceinline__ uint32_t pack2(__nv_bfloat16 lo16, __nv_bfloat16 hi16) {
    __nv_bfloat162 t = __halves2bfloat162(lo16, hi16);
    return *reinterpret_cast<uint32_t*>(&t);
}

// swizzled offset for 128B rows: chunk = 16B unit index 0..7
#define SWZ(row, chunk) (((row) * 128) + ((((chunk) ^ ((row) & 7)) & 7) << 4))

// ---------------------------------------------------------------------------
// fp32 -> hi/lo bf16 converters
// ---------------------------------------------------------------------------
__global__ __launch_bounds__(256)
void cvt_x_kernel(const float* __restrict__ x,
                  __nv_bfloat16* __restrict__ hi, __nv_bfloat16* __restrict__ lo)
{
    int i = (blockIdx.x * 256 + threadIdx.x) * 4;
    float4 v = *(const float4*)(x + i);
    __nv_bfloat16 h[4], l[4];
    split2(v.x, h[0], l[0]); split2(v.y, h[1], l[1]);
    split2(v.z, h[2], l[2]); split2(v.w, h[3], l[3]);
    *(uint2*)(hi + i) = make_uint2(pack2(h[0], h[1]), pack2(h[2], h[3]));
    *(uint2*)(lo + i) = make_uint2(pack2(l[0], l[1]), pack2(l[2], l[3]));
}

__global__ __launch_bounds__(256)
void cvt_w_kernel(const float* __restrict__ W0, const float* __restrict__ W1,
                  const float* __restrict__ W2,
                  __nv_bfloat16* __restrict__ Hbase, __nv_bfloat16* __restrict__ Lbase)
{
    __shared__ float tile[32][33];
    const float* W = blockIdx.z == 0 ? W0 : (blockIdx.z == 1 ? W1 : W2);
    __nv_bfloat16* Hh = Hbase + (size_t)blockIdx.z * H_ * H_;
    __nv_bfloat16* Ll = Lbase + (size_t)blockIdx.z * H_ * H_;
    int tx = threadIdx.x & 31, ty = threadIdx.x >> 5;
    int k0 = blockIdx.y * 32, n0 = blockIdx.x * 32;
#pragma unroll
    for (int i = 0; i < 4; i++)
        tile[ty + i * 8][tx] = W[(size_t)(k0 + ty + i * 8) * H_ + n0 + tx];
    __syncthreads();
#pragma unroll
    for (int i = 0; i < 4; i++) {
        int n = n0 + ty + i * 8;
        int k = k0 + tx;
        __nv_bfloat16 h, l;
        split2(tile[tx][ty + i * 8], h, l);
        Hh[(size_t)n * H_ + k] = h;
        Ll[(size_t)n * H_ + k] = l;
    }
}

// ---------------------------------------------------------------------------
// Projection GEMM: 128x128 tile, Kc=16, 4-stage cp.async pipeline, 2 CTAs/SM.
// grid (8 n-tiles, 64 m-tiles, 3 projections), 256 threads (8 warps: 4m x 2n).
// ---------------------------------------------------------------------------
#define PR_TILE (128 * PADW * 2)                // 6144 B per matrix tile
#define PR_STAGE (4 * PR_TILE)                  // 24576 B
#define PR_NST 4
#define PR_SMEM (PR_NST * PR_STAGE)             // 98304 B
#define PR_STAGES 64                            // K=1024 / 16

struct ProjArgs {
    const float *b0, *b1, *b2;
    const float *e0, *e1, *e2;
    const int* idx;
};

__global__ __launch_bounds__(256, 2)
void proj_mma_kernel(ProjArgs pa)
{
    extern __shared__ char smem[];
    const uint32_t sbase = smem_to_u32(smem);
    const int tid = threadIdx.x;
    const int lane = tid & 31;
    const int wid = tid >> 5;
    const int widm = wid & 3;
    const int widn = wid >> 2;
    const int n0 = blockIdx.x * 128;
    const int m0 = blockIdx.y * 128;
    const int z  = blockIdx.z;

    const __nv_bfloat16* Xh = g_Xh + (size_t)m0 * H_;
    const __nv_bfloat16* Xl = g_Xl + (size_t)m0 * H_;
    const __nv_bfloat16* Wh = g_Wh[z] + (size_t)n0 * H_;
    const __nv_bfloat16* Wl = g_Wl[z] + (size_t)n0 * H_;

    // Kc=16: each tile row = 16 bf16 = 32B = 2 cp.async chunks; 256 chunks/tile.
    const int lrow = tid >> 1;          // 0..127
    const int lc   = tid & 1;           // chunk 0/1
    auto load_stage = [&](int stage, int buf) {
        uint32_t sb = sbase + buf * PR_STAGE;
        const __nv_bfloat16* srcs[4] = { Xh, Xl, Wh, Wl };
#pragma unroll
        for (int t = 0; t < 4; t++) {
            const __nv_bfloat16* src = srcs[t] + stage * 16 + (size_t)lrow * H_ + lc * 8;
            CP_ASYNC16(sb + t * PR_TILE + lrow * (PADW * 2) + lc * 16, src);
        }
    };

    float acc[2][8][4];
#pragma unroll
    for (int i = 0; i < 2; i++)
#pragma unroll
        for (int j = 0; j < 8; j++)
#pragma unroll
            for (int c = 0; c < 4; c++) acc[i][j][c] = 0.f;

    load_stage(0, 0); CP_COMMIT();
    load_stage(1, 1); CP_COMMIT();
    load_stage(2, 2); CP_COMMIT();

    const int l16 = lane & 15;
    const int achunk = (lane >> 4);          // 16B unit within 32B row
    const int bchunk = ((lane >> 3) & 1);

    for (int s = 0; s < PR_STAGES; s++) {
        const int buf = s & (PR_NST - 1);
        CP_WAIT2();
        __syncthreads();
        if (s + 3 < PR_STAGES) { load_stage(s + 3, (s + 3) & (PR_NST - 1)); CP_COMMIT(); }

        const uint32_t sb = sbase + buf * PR_STAGE;
        uint32_t Ah[2][4], Al[2][4];
#pragma unroll
        for (int i = 0; i < 2; i++) {
            int r = widm * 32 + i * 16 + l16;
            ldm_x4(Ah[i], sb + 0 * PR_TILE + r * (PADW * 2) + achunk * 16);
            ldm_x4(Al[i], sb + 1 * PR_TILE + r * (PADW * 2) + achunk * 16);
        }
#pragma unroll
        for (int j = 0; j < 8; j += 2) {
            uint32_t Bh[4], Bl[4];
            int rb = widn * 64 + (j + (lane >> 4)) * 8 + (lane & 7);
            ldm_x4(Bh, sb + 2 * PR_TILE + rb * (PADW * 2) + bchunk * 16);
            ldm_x4(Bl, sb + 3 * PR_TILE + rb * (PADW * 2) + bchunk * 16);
#pragma unroll
            for (int i = 0; i < 2; i++) {
                mma_bf16(acc[i][j],     Ah[i], Bh);
                mma_bf16(acc[i][j],     Ah[i], Bl);
                mma_bf16(acc[i][j],     Al[i], Bh);
                mma_bf16(acc[i][j + 1], Ah[i], Bh + 2);
                mma_bf16(acc[i][j + 1], Ah[i], Bl + 2);
                mma_bf16(acc[i][j + 1], Al[i], Bh + 2);
            }
        }
        __syncthreads();
    }

    // Epilogue
    const float* bias = z == 0 ? pa.b0 : (z == 1 ? pa.b1 : pa.b2);
    const float* emb  = (z == 0 ? pa.e0 : (z == 1 ? pa.e1 : pa.e2)) + (size_t)(*pa.idx) * H_;
    __nv_bfloat16* Oh = g_Ph[z];
    __nv_bfloat16* Ol = g_Pl[z];

#pragma unroll
    for (int i = 0; i < 2; i++) {
#pragma unroll
        for (int j = 0; j < 8; j++) {
            int n = n0 + widn * 64 + j * 8 + 2 * (lane & 3);
            float b0v = bias[n] + emb[n];
            float b1v = bias[n + 1] + emb[n + 1];
            int hh = n >> 6, d = n & 63;
#pragma unroll
            for (int half = 0; half < 2; half++) {
                int m = m0 + widm * 32 + i * 16 + (lane >> 2) + half * 8;
                int bb = m >> 11, ss = m & (S_ - 1);
                float v0 = acc[i][j][half * 2 + 0] + b0v;
                float v1 = acc[i][j][half * 2 + 1] + b1v;
                __nv_bfloat16 h0, l0, h1, l1;
                split2(v0, h0, l0);
                split2(v1, h1, l1);
                size_t off = (((size_t)(bb * NH_ + hh)) * S_ + ss) * HD_ + d;
                *(uint32_t*)(Oh + off) = pack2(h0, h1);
                *(uint32_t*)(Ol + off) = pack2(l0, l1);
            }
        }
    }
}

// ---------------------------------------------------------------------------
// Flash attention, no-max softmax, jj-interleaved QK->exp->PV subtiles.
// grid (16 q-tiles, 64 bh), 256 threads (8 warps, 16 q-rows each).
// ---------------------------------------------------------------------------
#define AT_QH 0
#define AT_QL 16384
#define AT_BUF0 32768
#define KV_TILE 8192
#define BUF_STRIDE (4 * KV_TILE + 256)           // 33024
#define AT_SMEM (AT_BUF0 + 2 * BUF_STRIDE)       // 98816

__global__ __launch_bounds__(256, 2)
void attn_mma_kernel(const float* __restrict__ mask, float* __restrict__ out)
{
    extern __shared__ char smem[];
    const uint32_t sbase = smem_to_u32(smem);

    const int tid = threadIdx.x;
    const int lane = tid & 31;
    const int wid = tid >> 5;
    const int bh = blockIdx.y;
    const int b  = bh >> 4;
    const int hh = bh & 15;
    const int q0 = blockIdx.x * 128;

    const __nv_bfloat16* QhG = g_Ph[0] + ((size_t)bh * S_ + q0) * HD_;
    const __nv_bfloat16* QlG = g_Pl[0] + ((size_t)bh * S_ + q0) * HD_;
    const __nv_bfloat16* KhG = g_Ph[1] + (size_t)bh * S_ * HD_;
    const __nv_bfloat16* KlG = g_Pl[1] + (size_t)bh * S_ * HD_;
    const __nv_bfloat16* VhG = g_Ph[2] + (size_t)bh * S_ * HD_;
    const __nv_bfloat16* VlG = g_Pl[2] + (size_t)bh * S_ * HD_;
    const float* maskG = mask + (size_t)b * S_;

    auto load_kv = [&](int kt, int buf) {
        const __nv_bfloat16* srcs[4] = { KhG, KlG, VhG, VlG };
        uint32_t bb0 = sbase + AT_BUF0 + buf * BUF_STRIDE;
#pragma unroll
        for (int t = 0; t < 4; t++) {
#pragma unroll
            for (int p = 0; p < 2; p++) {
                int id = tid + p * 256;
                int row = id >> 3, c8 = id & 7;
                uint32_t dst = bb0 + t * KV_TILE + SWZ(row, c8);
                CP_ASYNC16(dst, srcs[t] + (size_t)(kt + row) * HD_ + c8 * 8);
            }
        }
        if (tid < 16)
            CP_ASYNC16(bb0 + 4 * KV_TILE + tid * 16, maskG + kt + tid * 4);
    };

    // Q tile via cp.async (own group), then kv0
#pragma unroll
    for (int p = 0; p < 4; p++) {
        int id = tid + p * 256;
        int row = id >> 3, c8 = id & 7;
        uint32_t so = SWZ(row, c8);
        CP_ASYNC16(sbase + AT_QH + so, QhG + (size_t)row * HD_ + c8 * 8);
        CP_ASYNC16(sbase + AT_QL + so, QlG + (size_t)row * HD_ + c8 * 8);
    }
    CP_COMMIT();
    load_kv(0, 0);
    CP_COMMIT();

    CP_WAIT1();
    __syncthreads();

    const int l16 = lane & 15;
    uint32_t Qh[4][4], Ql[4][4];
#pragma unroll
    for (int kk = 0; kk < 4; kk++) {
        const int achk = kk * 2 + (lane >> 4);
        const int ra = wid * 16 + l16;
        ldm_x4(Qh[kk], sbase + AT_QH + SWZ(ra, achk));
        ldm_x4(Ql[kk], sbase + AT_QL + SWZ(ra, achk));
    }

    float o[8][4];
#pragma unroll
    for (int j = 0; j < 8; j++)
#pragma unroll
        for (int c = 0; c < 4; c++) o[j][c] = 0.f;
    float lrow[2] = {0.f, 0.f};   // per-thread partial denominators

    const float SC = 0.125f * LOG2E;
    const int mcol = 2 * (lane & 3);

    for (int it = 0; it < S_ / 64; it++) {
        const int buf = it & 1;
        if (it < S_ / 64 - 1) { load_kv((it + 1) * 64, buf ^ 1); CP_COMMIT(); CP_WAIT1(); }
        else                  { CP_WAIT0(); }
        __syncthreads();

        const uint32_t kb = sbase + AT_BUF0 + buf * BUF_STRIDE;
        const float* mask_s = (const float*)(smem + AT_BUF0 + buf * BUF_STRIDE + 4 * KV_TILE);

        // Interleaved: per 16-key subtile jj, QK -> exp -> PV.
#pragma unroll
        for (int jj = 0; jj < 4; jj++) {
            float s2[2][4];
#pragma unroll
            for (int c = 0; c < 4; c++) { s2[0][c] = 0.f; s2[1][c] = 0.f; }

            // ---- QK for columns [jj*16, jj*16+16) ----
            int rb = (2 * jj + (lane >> 4)) * 8 + (lane & 7);
#pragma unroll
            for (int kk = 0; kk < 4; kk++) {
                const int bchk = kk * 2 + ((lane >> 3) & 1);
                uint32_t Bh[4], Bl[4];
                ldm_x4(Bh, kb + 0 * KV_TILE + SWZ(rb, bchk));
                ldm_x4(Bl, kb + 1 * KV_TILE + SWZ(rb, bchk));
                mma_bf16(s2[0], Qh[kk], Bh);
                mma_bf16(s2[0], Qh[kk], Bl);
                mma_bf16(s2[0], Ql[kk], Bh);
                mma_bf16(s2[1], Qh[kk], Bh + 2);
                mma_bf16(s2[1], Qh[kk], Bl + 2);
                mma_bf16(s2[1], Ql[kk], Bh + 2);
            }

            // ---- p = exp2(s*SC + mask*log2e) ----
            {
                float ma0 = mask_s[(2 * jj) * 8 + mcol] * LOG2E;
                float ma1 = mask_s[(2 * jj) * 8 + mcol + 1] * LOG2E;
                float mb0 = mask_s[(2 * jj + 1) * 8 + mcol] * LOG2E;
                float mb1 = mask_s[(2 * jj + 1) * 8 + mcol + 1] * LOG2E;
                s2[0][0] = ex2(fmaf(s2[0][0], SC, ma0));
                s2[0][1] = ex2(fmaf(s2[0][1], SC, ma1));
                s2[0][2] = ex2(fmaf(s2[0][2], SC, ma0));
                s2[0][3] = ex2(fmaf(s2[0][3], SC, ma1));
                s2[1][0] = ex2(fmaf(s2[1][0], SC, mb0));
                s2[1][1] = ex2(fmaf(s2[1][1], SC, mb1));
                s2[1][2] = ex2(fmaf(s2[1][2], SC, mb0));
                s2[1][3] = ex2(fmaf(s2[1][3], SC, mb1));
                lrow[0] += s2[0][0] + s2[0][1] + s2[1][0] + s2[1][1];
                lrow[1] += s2[0][2] + s2[0][3] + s2[1][2] + s2[1][3];
            }

            // ---- split P to hi/lo fragments ----
            uint32_t Ph[4], Pl[4];
            {
                __nv_bfloat16 h0, l0, h1, l1;
                split2(s2[0][0], h0, l0);  split2(s2[0][1], h1, l1);
                Ph[0] = pack2(h0, h1); Pl[0] = pack2(l0, l1);
                split2(s2[0][2], h0, l0);  split2(s2[0][3], h1, l1);
                Ph[1] = pack2(h0, h1); Pl[1] = pack2(l0, l1);
                split2(s2[1][0], h0, l0);  split2(s2[1][1], h1, l1);
                Ph[2] = pack2(h0, h1); Pl[2] = pack2(l0, l1);
                split2(s2[1][2], h0, l0);  split2(s2[1][3], h1, l1);
                Ph[3] = pack2(h0, h1); Pl[3] = pack2(l0, l1);
            }

            // ---- PV for this key subtile ----
            int rv = jj * 16 + (lane & 7) + ((lane >> 3) & 1) * 8;
#pragma unroll
            for (int j = 0; j < 8; j += 2) {
                uint32_t Vh[4], Vl[4];
                int chk = j + (lane >> 4);
                ldm_x4t(Vh, kb + 2 * KV_TILE + SWZ(rv, chk));
                ldm_x4t(Vl, kb + 3 * KV_TILE + SWZ(rv, chk));
                mma_bf16(o[j],     Ph, Vh);
                mma_bf16(o[j],     Ph, Vl);
                mma_bf16(o[j],     Pl, Vh);
                mma_bf16(o[j + 1], Ph, Vh + 2);
                mma_bf16(o[j + 1], Ph, Vl + 2);
                mma_bf16(o[j + 1], Pl, Vh + 2);
            }
        }
        __syncthreads();
    }

    // ---- one-time denominator reduce across the 4 threads of each row ----
#pragma unroll
    for (int w = 1; w <= 2; w <<= 1) {
        lrow[0] += __shfl_xor_sync(0xffffffffu, lrow[0], w);
        lrow[1] += __shfl_xor_sync(0xffffffffu, lrow[1], w);
    }

    // ---- epilogue ----
    float inv0 = 1.f / lrow[0];
    float inv1 = 1.f / lrow[1];
#pragma unroll
    for (int j = 0; j < 8; j++) {
        int d = j * 8 + 2 * (lane & 3);
        int r0 = q0 + wid * 16 + (lane >> 2);
        float2 v0 = make_float2(o[j][0] * inv0, o[j][1] * inv0);
        float2 v1 = make_float2(o[j][2] * inv1, o[j][3] * inv1);
        *(float2*)(out + ((size_t)b * S_ + r0) * H_ + hh * HD_ + d) = v0;
        *(float2*)(out + ((size_t)b * S_ + r0 + 8) * H_ + hh * HD_ + d) = v1;
    }
}

// ---------------------------------------------------------------------------
extern "C" void kernel_launch(void* const* d_in, const int* in_sizes, int n_in,
                              void* d_out, int out_size)
{
    const float* X    = (const float*)d_in[0];
    const float* mask = (const float*)d_in[1];
    const float* Wq   = (const float*)d_in[2];
    const float* bq   = (const float*)d_in[3];
    const float* Wk   = (const float*)d_in[4];
    const float* bk   = (const float*)d_in[5];
    const float* Wv   = (const float*)d_in[6];
    const float* bv   = (const float*)d_in[7];
    const float* qe   = (const float*)d_in[8];
    const float* ke   = (const float*)d_in[9];
    const float* ve   = (const float*)d_in[10];
    const int*   idx  = (const int*)d_in[11];
    float* out = (float*)d_out;

    __nv_bfloat16 *Xh, *Xl, *Whb, *Wlb;
    cudaGetSymbolAddress((void**)&Xh, g_Xh);
    cudaGetSymbolAddress((void**)&Xl, g_Xl);
    cudaGetSymbolAddress((void**)&Whb, g_Wh);
    cudaGetSymbolAddress((void**)&Wlb, g_Wl);

    cvt_x_kernel<<<(B_ * S_ * H_) / (256 * 4), 256>>>(X, Xh, Xl);
    {
        dim3 g(H_ / 32, H_ / 32, 3);
        cvt_w_kernel<<<g, 256>>>(Wq, Wk, Wv, Whb, Wlb);
    }

    ProjArgs pa;
    pa.b0 = bq; pa.b1 = bk; pa.b2 = bv;
    pa.e0 = qe; pa.e1 = ke; pa.e2 = ve;
    pa.idx = idx;
    cudaFuncSetAttribute(proj_mma_kernel, cudaFuncAttributeMaxDynamicSharedMemorySize, PR_SMEM);
    cudaFuncSetAttribute(proj_mma_kernel, cudaFuncAttributePreferredSharedMemoryCarveout, 100);
    dim3 pgrid(H_ / 128, (B_ * S_) / 128, 3);   // (8, 64, 3)
    proj_mma_kernel<<<pgrid, 256, PR_SMEM>>>(pa);

    cudaFuncSetAttribute(attn_mma_kernel, cudaFuncAttributeMaxDynamicSharedMemorySize, AT_SMEM);
    cudaFuncSetAttribute(attn_mma_kernel, cudaFuncAttributePreferredSharedMemoryCarveout, 100);
    dim3 agrid(S_ / 128, B_ * NH_);
    attn_mma_kernel<<<agrid, 256, AT_SMEM>>>(mask, out);
}

// round 15
// speedup vs baseline: 1.0727x; 1.0727x over previous
#include <cuda_runtime.h>
#include <cuda_bf16.h>
#include <cstdint>

#define B_  4
#define S_  2048
#define H_  1024
#define NH_ 16
#define HD_ 64

#define LOG2E 1.4426950408889634f
#define PADW 40   // proj: bf16 elems per SMEM row (80B), Kc=32

// ---------------------------------------------------------------------------
__device__ __nv_bfloat16 g_Xh[B_ * S_ * H_];
__device__ __nv_bfloat16 g_Xl[B_ * S_ * H_];
__device__ __nv_bfloat16 g_Wh[3][H_ * H_];   // W^T: [N][K]
__device__ __nv_bfloat16 g_Wl[3][H_ * H_];
__device__ __nv_bfloat16 g_Ph[3][B_ * NH_ * S_ * HD_];  // Q/K/V hi, [bh][s][d]
__device__ __nv_bfloat16 g_Pl[3][B_ * NH_ * S_ * HD_];  // Q/K/V lo

// ---------------------------------------------------------------------------
__device__ __forceinline__ uint32_t smem_to_u32(const void* p) {
    uint32_t a;
    asm("{ .reg .u64 t; cvta.to.shared.u64 t, %1; cvt.u32.u64 %0, t; }"
        : "=r"(a) : "l"(p));
    return a;
}

__device__ __forceinline__ void mma_bf16(float* c, const uint32_t* a, const uint32_t* b) {
    asm volatile(
        "mma.sync.aligned.m16n8k16.row.col.f32.bf16.bf16.f32 "
        "{%0,%1,%2,%3}, {%4,%5,%6,%7}, {%8,%9}, {%0,%1,%2,%3};"
        : "+f"(c[0]), "+f"(c[1]), "+f"(c[2]), "+f"(c[3])
        : "r"(a[0]), "r"(a[1]), "r"(a[2]), "r"(a[3]), "r"(b[0]), "r"(b[1]));
}

__device__ __forceinline__ void ldm_x4(uint32_t* r, uint32_t addr) {
    asm volatile("ldmatrix.sync.aligned.m8n8.x4.shared.b16 {%0,%1,%2,%3}, [%4];"
        : "=r"(r[0]), "=r"(r[1]), "=r"(r[2]), "=r"(r[3]) : "r"(addr));
}
__device__ __forceinline__ void ldm_x4t(uint32_t* r, uint32_t addr) {
    asm volatile("ldmatrix.sync.aligned.m8n8.x4.trans.shared.b16 {%0,%1,%2,%3}, [%4];"
        : "=r"(r[0]), "=r"(r[1]), "=r"(r[2]), "=r"(r[3]) : "r"(addr));
}

#define CP_ASYNC16(dst, src) \
    asm volatile("cp.async.cg.shared.global [%0], [%1], 16;" :: "r"(dst), "l"(src))
#define CP_COMMIT() asm volatile("cp.async.commit_group;")
#define CP_WAIT1()  asm volatile("cp.async.wait_group 1;" ::: "memory")
#define CP_WAIT0()  asm volatile("cp.async.wait_group 0;" ::: "memory")

__device__ __forceinline__ float ex2(float x) {
    float y;
    asm("ex2.approx.ftz.f32 %0, %1;" : "=f"(y) : "f"(x));
    return y;
}

__device__ __forceinline__ void split2(float x, __nv_bfloat16& h, __nv_bfloat16& l) {
    h = __float2bfloat16(x);
    l = __float2bfloat16(x - __bfloat162float(h));
}
__device__ __forceinline__ uint32_t pack2(__nv_bfloat16 lo16, __nv_bfloat16 hi16) {
    __nv_bfloat162 t = __halves2bfloat162(lo16, hi16);
    return *reinterpret_cast<uint32_t*>(&t);
}

// swizzled offset for 128B rows: chunk = 16B unit index 0..7
#define SWZ(row, chunk) (((row) * 128) + ((((chunk) ^ ((row) & 7)) & 7) << 4))

// ---------------------------------------------------------------------------
// fp32 -> hi/lo bf16 converters
// ---------------------------------------------------------------------------
__global__ __launch_bounds__(256)
void cvt_x_kernel(const float* __restrict__ x,
                  __nv_bfloat16* __restrict__ hi, __nv_bfloat16* __restrict__ lo)
{
    int i = (blockIdx.x * 256 + threadIdx.x) * 4;
    float4 v = *(const float4*)(x + i);
    __nv_bfloat16 h[4], l[4];
    split2(v.x, h[0], l[0]); split2(v.y, h[1], l[1]);
    split2(v.z, h[2], l[2]); split2(v.w, h[3], l[3]);
    *(uint2*)(hi + i) = make_uint2(pack2(h[0], h[1]), pack2(h[2], h[3]));
    *(uint2*)(lo + i) = make_uint2(pack2(l[0], l[1]), pack2(l[2], l[3]));
}

__global__ __launch_bounds__(256)
void cvt_w_kernel(const float* __restrict__ W0, const float* __restrict__ W1,
                  const float* __restrict__ W2,
                  __nv_bfloat16* __restrict__ Hbase, __nv_bfloat16* __restrict__ Lbase)
{
    __shared__ float tile[32][33];
    const float* W = blockIdx.z == 0 ? W0 : (blockIdx.z == 1 ? W1 : W2);
    __nv_bfloat16* Hh = Hbase + (size_t)blockIdx.z * H_ * H_;
    __nv_bfloat16* Ll = Lbase + (size_t)blockIdx.z * H_ * H_;
    int tx = threadIdx.x & 31, ty = threadIdx.x >> 5;
    int k0 = blockIdx.y * 32, n0 = blockIdx.x * 32;
#pragma unroll
    for (int i = 0; i < 4; i++)
        tile[ty + i * 8][tx] = W[(size_t)(k0 + ty + i * 8) * H_ + n0 + tx];
    __syncthreads();
#pragma unroll
    for (int i = 0; i < 4; i++) {
        int n = n0 + ty + i * 8;
        int k = k0 + tx;
        __nv_bfloat16 h, l;
        split2(tile[tx][ty + i * 8], h, l);
        Hh[(size_t)n * H_ + k] = h;
        Ll[(size_t)n * H_ + k] = l;
    }
}

// ---------------------------------------------------------------------------
// Projection GEMM: 128x128 tile, Kc=32, 2 CTAs/SM, x4-merged B fragments,
// smem-staged coalesced epilogue.
// grid (8 n-tiles, 64 m-tiles, 3 projections), 256 threads (8 warps: 4m x 2n).
// ---------------------------------------------------------------------------
#define PR_TILE (128 * PADW * 2)                // 10240 B per matrix tile
#define PR_STAGE (4 * PR_TILE)                  // 40960 B
#define PR_SMEM (2 * PR_STAGE)                  // 81920 B (also covers 128*136*4 epilogue)
#define SMP 136                                 // epilogue smem row stride (floats)

struct ProjArgs {
    const float *b0, *b1, *b2;
    const float *e0, *e1, *e2;
    const int* idx;
};

__global__ __launch_bounds__(256, 2)
void proj_mma_kernel(ProjArgs pa)
{
    extern __shared__ char smem[];
    const uint32_t sbase = smem_to_u32(smem);
    const int tid = threadIdx.x;
    const int lane = tid & 31;
    const int wid = tid >> 5;
    const int widm = wid & 3;
    const int widn = wid >> 2;
    const int n0 = blockIdx.x * 128;
    const int m0 = blockIdx.y * 128;
    const int z  = blockIdx.z;

    const __nv_bfloat16* Xh = g_Xh + (size_t)m0 * H_;
    const __nv_bfloat16* Xl = g_Xl + (size_t)m0 * H_;
    const __nv_bfloat16* Wh = g_Wh[z] + (size_t)n0 * H_;
    const __nv_bfloat16* Wl = g_Wl[z] + (size_t)n0 * H_;

    auto load_stage = [&](int stage, int buf) {
        const __nv_bfloat16* srcs[4] = { Xh, Xl, Wh, Wl };
        uint32_t sb = sbase + buf * PR_STAGE;
#pragma unroll
        for (int t = 0; t < 4; t++) {
            const __nv_bfloat16* src = srcs[t] + stage * 32;
#pragma unroll
            for (int p = 0; p < 2; p++) {
                int id = tid + p * 256;
                int row = id >> 2, c4 = id & 3;
                uint32_t dst = sb + t * PR_TILE + (row * PADW + c4 * 8) * 2;
                CP_ASYNC16(dst, src + (size_t)row * H_ + c4 * 8);
            }
        }
    };

    float acc[2][8][4];
#pragma unroll
    for (int i = 0; i < 2; i++)
#pragma unroll
        for (int j = 0; j < 8; j++)
#pragma unroll
            for (int c = 0; c < 4; c++) acc[i][j][c] = 0.f;

    load_stage(0, 0);
    CP_COMMIT();

    const int l16 = lane & 15;

    for (int s = 0; s < 32; s++) {
        const int buf = s & 1;
        if (s < 31) { load_stage(s + 1, buf ^ 1); CP_COMMIT(); CP_WAIT1(); }
        else        { CP_WAIT0(); }
        __syncthreads();

        const uint32_t sb = sbase + buf * PR_STAGE;
#pragma unroll
        for (int kk = 0; kk < 2; kk++) {
            uint32_t Ah[2][4], Al[2][4];
            const int acol = kk * 16 + (lane >> 4) * 8;
#pragma unroll
            for (int i = 0; i < 2; i++) {
                int r = widm * 32 + i * 16 + l16;
                ldm_x4(Ah[i], sb + 0 * PR_TILE + (r * PADW + acol) * 2);
                ldm_x4(Al[i], sb + 1 * PR_TILE + (r * PADW + acol) * 2);
            }
            const int bcol = kk * 16 + ((lane >> 3) & 1) * 8;
#pragma unroll
            for (int j = 0; j < 8; j += 2) {
                uint32_t Bh[4], Bl[4];
                int rb = widn * 64 + (j + (lane >> 4)) * 8 + (lane & 7);
                ldm_x4(Bh, sb + 2 * PR_TILE + (rb * PADW + bcol) * 2);
                ldm_x4(Bl, sb + 3 * PR_TILE + (rb * PADW + bcol) * 2);
#pragma unroll
                for (int i = 0; i < 2; i++) {
                    mma_bf16(acc[i][j],     Ah[i], Bh);
                    mma_bf16(acc[i][j],     Ah[i], Bl);
                    mma_bf16(acc[i][j],     Al[i], Bh);
                    mma_bf16(acc[i][j + 1], Ah[i], Bh + 2);
                    mma_bf16(acc[i][j + 1], Ah[i], Bl + 2);
                    mma_bf16(acc[i][j + 1], Al[i], Bh + 2);
                }
            }
        }
        __syncthreads();
    }

    // ---- epilogue: stage through smem, emit coalesced 128B row stores ----
    const float* bias = z == 0 ? pa.b0 : (z == 1 ? pa.b1 : pa.b2);
    const float* emb  = (z == 0 ? pa.e0 : (z == 1 ? pa.e1 : pa.e2)) + (size_t)(*pa.idx) * H_;
    __nv_bfloat16* Oh = g_Ph[z];
    __nv_bfloat16* Ol = g_Pl[z];

    float* smf = (float*)smem;
#pragma unroll
    for (int i = 0; i < 2; i++)
#pragma unroll
        for (int j = 0; j < 8; j++)
#pragma unroll
            for (int half = 0; half < 2; half++) {
                int m  = widm * 32 + i * 16 + (lane >> 2) + half * 8;
                int nn = widn * 64 + j * 8 + 2 * (lane & 3);
                *(float2*)&smf[m * SMP + nn] =
                    make_float2(acc[i][j][half * 2], acc[i][j][half * 2 + 1]);
            }
    __syncthreads();

    // read phase: lane sweeps d (coalesced), warp sweeps (m, head) rows
    float2 bn[2];
#pragma unroll
    for (int hs = 0; hs < 2; hs++) {
        int n = n0 + hs * 64 + 2 * lane;
        bn[hs] = make_float2(bias[n] + emb[n], bias[n + 1] + emb[n + 1]);
    }
    const int hg0 = n0 >> 6;
#pragma unroll
    for (int t = 0; t < 32; t++) {
        int r = t * 8 + wid;
        int m = r >> 1, hs = r & 1;
        float2 v = *(float2*)&smf[m * SMP + hs * 64 + 2 * lane];
        v.x += bn[hs].x;
        v.y += bn[hs].y;
        int mg = m0 + m;
        int bb = mg >> 11, ss = mg & (S_ - 1);
        __nv_bfloat16 h0, l0, h1, l1;
        split2(v.x, h0, l0);
        split2(v.y, h1, l1);
        size_t off = (((size_t)(bb * NH_ + hg0 + hs)) * S_ + ss) * HD_ + 2 * lane;
        *(uint32_t*)(Oh + off) = pack2(h0, h1);
        *(uint32_t*)(Ol + off) = pack2(l0, l1);
    }
}

// ---------------------------------------------------------------------------
// Flash attention, no-max softmax, jj-interleaved QK->exp->PV subtiles.
// grid (16 q-tiles, 64 bh), 256 threads (8 warps, 16 q-rows each).
// ---------------------------------------------------------------------------
#define AT_QH 0
#define AT_QL 16384
#define AT_BUF0 32768
#define KV_TILE 8192
#define BUF_STRIDE (4 * KV_TILE + 256)           // 33024
#define AT_SMEM (AT_BUF0 + 2 * BUF_STRIDE)       // 98816

__global__ __launch_bounds__(256, 2)
void attn_mma_kernel(const float* __restrict__ mask, float* __restrict__ out)
{
    extern __shared__ char smem[];
    const uint32_t sbase = smem_to_u32(smem);

    const int tid = threadIdx.x;
    const int lane = tid & 31;
    const int wid = tid >> 5;
    const int bh = blockIdx.y;
    const int b  = bh >> 4;
    const int hh = bh & 15;
    const int q0 = blockIdx.x * 128;

    const __nv_bfloat16* QhG = g_Ph[0] + ((size_t)bh * S_ + q0) * HD_;
    const __nv_bfloat16* QlG = g_Pl[0] + ((size_t)bh * S_ + q0) * HD_;
    const __nv_bfloat16* KhG = g_Ph[1] + (size_t)bh * S_ * HD_;
    const __nv_bfloat16* KlG = g_Pl[1] + (size_t)bh * S_ * HD_;
    const __nv_bfloat16* VhG = g_Ph[2] + (size_t)bh * S_ * HD_;
    const __nv_bfloat16* VlG = g_Pl[2] + (size_t)bh * S_ * HD_;
    const float* maskG = mask + (size_t)b * S_;

    auto load_kv = [&](int kt, int buf) {
        const __nv_bfloat16* srcs[4] = { KhG, KlG, VhG, VlG };
        uint32_t bb0 = sbase + AT_BUF0 + buf * BUF_STRIDE;
#pragma unroll
        for (int t = 0; t < 4; t++) {
#pragma unroll
            for (int p = 0; p < 2; p++) {
                int id = tid + p * 256;
                int row = id >> 3, c8 = id & 7;
                uint32_t dst = bb0 + t * KV_TILE + SWZ(row, c8);
                CP_ASYNC16(dst, srcs[t] + (size_t)(kt + row) * HD_ + c8 * 8);
            }
        }
        if (tid < 16)
            CP_ASYNC16(bb0 + 4 * KV_TILE + tid * 16, maskG + kt + tid * 4);
    };

    // Q tile via cp.async (own group), then kv0
#pragma unroll
    for (int p = 0; p < 4; p++) {
        int id = tid + p * 256;
        int row = id >> 3, c8 = id & 7;
        uint32_t so = SWZ(row, c8);
        CP_ASYNC16(sbase + AT_QH + so, QhG + (size_t)row * HD_ + c8 * 8);
        CP_ASYNC16(sbase + AT_QL + so, QlG + (size_t)row * HD_ + c8 * 8);
    }
    CP_COMMIT();
    load_kv(0, 0);
    CP_COMMIT();

    CP_WAIT1();
    __syncthreads();

    const int l16 = lane & 15;
    uint32_t Qh[4][4], Ql[4][4];
#pragma unroll
    for (int kk = 0; kk < 4; kk++) {
        const int achk = kk * 2 + (lane >> 4);
        const int ra = wid * 16 + l16;
        ldm_x4(Qh[kk], sbase + AT_QH + SWZ(ra, achk));
        ldm_x4(Ql[kk], sbase + AT_QL + SWZ(ra, achk));
    }

    float o[8][4];
#pragma unroll
    for (int j = 0; j < 8; j++)
#pragma unroll
        for (int c = 0; c < 4; c++) o[j][c] = 0.f;
    float lrow[2] = {0.f, 0.f};   // per-thread partial denominators

    const float SC = 0.125f * LOG2E;
    const int mcol = 2 * (lane & 3);

    for (int it = 0; it < S_ / 64; it++) {
        const int buf = it & 1;
        if (it < S_ / 64 - 1) { load_kv((it + 1) * 64, buf ^ 1); CP_COMMIT(); CP_WAIT1(); }
        else                  { CP_WAIT0(); }
        __syncthreads();

        const uint32_t kb = sbase + AT_BUF0 + buf * BUF_STRIDE;
        const float* mask_s = (const float*)(smem + AT_BUF0 + buf * BUF_STRIDE + 4 * KV_TILE);

        // Interleaved: per 16-key subtile jj, QK -> exp -> PV.
#pragma unroll
        for (int jj = 0; jj < 4; jj++) {
            float s2[2][4];
#pragma unroll
            for (int c = 0; c < 4; c++) { s2[0][c] = 0.f; s2[1][c] = 0.f; }

            // ---- QK for columns [jj*16, jj*16+16) ----
            int rb = (2 * jj + (lane >> 4)) * 8 + (lane & 7);
#pragma unroll
            for (int kk = 0; kk < 4; kk++) {
                const int bchk = kk * 2 + ((lane >> 3) & 1);
                uint32_t Bh[4], Bl[4];
                ldm_x4(Bh, kb + 0 * KV_TILE + SWZ(rb, bchk));
                ldm_x4(Bl, kb + 1 * KV_TILE + SWZ(rb, bchk));
                mma_bf16(s2[0], Qh[kk], Bh);
                mma_bf16(s2[0], Qh[kk], Bl);
                mma_bf16(s2[0], Ql[kk], Bh);
                mma_bf16(s2[1], Qh[kk], Bh + 2);
                mma_bf16(s2[1], Qh[kk], Bl + 2);
                mma_bf16(s2[1], Ql[kk], Bh + 2);
            }

            // ---- p = exp2(s*SC + mask*log2e) ----
            {
                float ma0 = mask_s[(2 * jj) * 8 + mcol] * LOG2E;
                float ma1 = mask_s[(2 * jj) * 8 + mcol + 1] * LOG2E;
                float mb0 = mask_s[(2 * jj + 1) * 8 + mcol] * LOG2E;
                float mb1 = mask_s[(2 * jj + 1) * 8 + mcol + 1] * LOG2E;
                s2[0][0] = ex2(fmaf(s2[0][0], SC, ma0));
                s2[0][1] = ex2(fmaf(s2[0][1], SC, ma1));
                s2[0][2] = ex2(fmaf(s2[0][2], SC, ma0));
                s2[0][3] = ex2(fmaf(s2[0][3], SC, ma1));
                s2[1][0] = ex2(fmaf(s2[1][0], SC, mb0));
                s2[1][1] = ex2(fmaf(s2[1][1], SC, mb1));
                s2[1][2] = ex2(fmaf(s2[1][2], SC, mb0));
                s2[1][3] = ex2(fmaf(s2[1][3], SC, mb1));
                lrow[0] += s2[0][0] + s2[0][1] + s2[1][0] + s2[1][1];
                lrow[1] += s2[0][2] + s2[0][3] + s2[1][2] + s2[1][3];
            }

            // ---- split P to hi/lo fragments ----
            uint32_t Ph[4], Pl[4];
            {
                __nv_bfloat16 h0, l0, h1, l1;
                split2(s2[0][0], h0, l0);  split2(s2[0][1], h1, l1);
                Ph[0] = pack2(h0, h1); Pl[0] = pack2(l0, l1);
                split2(s2[0][2], h0, l0);  split2(s2[0][3], h1, l1);
                Ph[1] = pack2(h0, h1); Pl[1] = pack2(l0, l1);
                split2(s2[1][0], h0, l0);  split2(s2[1][1], h1, l1);
                Ph[2] = pack2(h0, h1); Pl[2] = pack2(l0, l1);
                split2(s2[1][2], h0, l0);  split2(s2[1][3], h1, l1);
                Ph[3] = pack2(h0, h1); Pl[3] = pack2(l0, l1);
            }

            // ---- PV for this key subtile ----
            int rv = jj * 16 + (lane & 7) + ((lane >> 3) & 1) * 8;
#pragma unroll
            for (int j = 0; j < 8; j += 2) {
                uint32_t Vh[4], Vl[4];
                int chk = j + (lane >> 4);
                ldm_x4t(Vh, kb + 2 * KV_TILE + SWZ(rv, chk));
                ldm_x4t(Vl, kb + 3 * KV_TILE + SWZ(rv, chk));
                mma_bf16(o[j],     Ph, Vh);
                mma_bf16(o[j],     Ph, Vl);
                mma_bf16(o[j],     Pl, Vh);
                mma_bf16(o[j + 1], Ph, Vh + 2);
                mma_bf16(o[j + 1], Ph, Vl + 2);
                mma_bf16(o[j + 1], Pl, Vh + 2);
            }
        }
        __syncthreads();
    }

    // ---- one-time denominator reduce across the 4 threads of each row ----
#pragma unroll
    for (int w = 1; w <= 2; w <<= 1) {
        lrow[0] += __shfl_xor_sync(0xffffffffu, lrow[0], w);
        lrow[1] += __shfl_xor_sync(0xffffffffu, lrow[1], w);
    }

    // ---- epilogue ----
    float inv0 = 1.f / lrow[0];
    float inv1 = 1.f / lrow[1];
#pragma unroll
    for (int j = 0; j < 8; j++) {
        int d = j * 8 + 2 * (lane & 3);
        int r0 = q0 + wid * 16 + (lane >> 2);
        float2 v0 = make_float2(o[j][0] * inv0, o[j][1] * inv0);
        float2 v1 = make_float2(o[j][2] * inv1, o[j][3] * inv1);
        *(float2*)(out + ((size_t)b * S_ + r0) * H_ + hh * HD_ + d) = v0;
        *(float2*)(out + ((size_t)b * S_ + r0 + 8) * H_ + hh * HD_ + d) = v1;
    }
}

// ---------------------------------------------------------------------------
extern "C" void kernel_launch(void* const* d_in, const int* in_sizes, int n_in,
                              void* d_out, int out_size)
{
    const float* X    = (const float*)d_in[0];
    const float* mask = (const float*)d_in[1];
    const float* Wq   = (const float*)d_in[2];
    const float* bq   = (const float*)d_in[3];
    const float* Wk   = (const float*)d_in[4];
    const float* bk   = (const float*)d_in[5];
    const float* Wv   = (const float*)d_in[6];
    const float* bv   = (const float*)d_in[7];
    const float* qe   = (const float*)d_in[8];
    const float* ke   = (const float*)d_in[9];
    const float* ve   = (const float*)d_in[10];
    const int*   idx  = (const int*)d_in[11];
    float* out = (float*)d_out;

    __nv_bfloat16 *Xh, *Xl, *Whb, *Wlb;
    cudaGetSymbolAddress((void**)&Xh, g_Xh);
    cudaGetSymbolAddress((void**)&Xl, g_Xl);
    cudaGetSymbolAddress((void**)&Whb, g_Wh);
    cudaGetSymbolAddress((void**)&Wlb, g_Wl);

    cvt_x_kernel<<<(B_ * S_ * H_) / (256 * 4), 256>>>(X, Xh, Xl);
    {
        dim3 g(H_ / 32, H_ / 32, 3);
        cvt_w_kernel<<<g, 256>>>(Wq, Wk, Wv, Whb, Wlb);
    }

    ProjArgs pa;
    pa.b0 = bq; pa.b1 = bk; pa.b2 = bv;
    pa.e0 = qe; pa.e1 = ke; pa.e2 = ve;
    pa.idx = idx;
    cudaFuncSetAttribute(proj_mma_kernel, cudaFuncAttributeMaxDynamicSharedMemorySize, PR_SMEM);
    cudaFuncSetAttribute(proj_mma_kernel, cudaFuncAttributePreferredSharedMemoryCarveout, 100);
    dim3 pgrid(H_ / 128, (B_ * S_) / 128, 3);   // (8, 64, 3)
    proj_mma_kernel<<<pgrid, 256, PR_SMEM>>>(pa);

    cudaFuncSetAttribute(attn_mma_kernel, cudaFuncAttributeMaxDynamicSharedMemorySize, AT_SMEM);
    cudaFuncSetAttribute(attn_mma_kernel, cudaFuncAttributePreferredSharedMemoryCarveout, 100);
    dim3 agrid(S_ / 128, B_ * NH_);
    attn_mma_kernel<<<agrid, 256, AT_SMEM>>>(mask, out);
}